// round 7
// baseline (speedup 1.0000x reference)
#include <cuda_runtime.h>
#include <cuda_bf16.h>
#include <cstdint>
#include <cstddef>
#include <cstring>

// ---------------- problem constants ----------------
#define NN       26
#define KDIM     676
#define KPAD     704          // 22 * 32
#define NCHUNK   22
#define HID      256

// GAT output as bf16 hi/lo split [B, KPAD]
__device__ __nv_bfloat16 g_Ahi[16384 * KPAD];
__device__ __nv_bfloat16 g_Alo[16384 * KPAD];
// W1^T split: [256 n][KPAD k]
__device__ __nv_bfloat16 g_Bhi[256 * KPAD];
__device__ __nv_bfloat16 g_Blo[256 * KPAD];
// GAT weights, transposed + padded + split: [12 lh][32 o][40 f]
__device__ __nv_bfloat16 g_Wth[12 * 32 * 40];
__device__ __nv_bfloat16 g_Wtl[12 * 32 * 40];
// score vectors wsrc/wdst = W @ a_*: [12 lh][32 f]
__device__ float g_wsrc[12 * 32];
__device__ float g_wdst[12 * 32];

// ---------------- common helpers ----------------
__device__ __forceinline__ uint32_t smem_u32(const void* p) {
    uint32_t a;
    asm("{ .reg .u64 t; cvta.to.shared.u64 t, %1; cvt.u32.u64 %0, t; }" : "=r"(a) : "l"(p));
    return a;
}
__device__ __forceinline__ void ldsm4(uint32_t* d, uint32_t addr) {
    asm volatile("ldmatrix.sync.aligned.m8n8.x4.shared.b16 {%0,%1,%2,%3}, [%4];"
                 : "=r"(d[0]), "=r"(d[1]), "=r"(d[2]), "=r"(d[3]) : "r"(addr));
}
__device__ __forceinline__ void mma16816(float* c, const uint32_t* a, uint32_t b0, uint32_t b1) {
    asm volatile(
        "mma.sync.aligned.m16n8k16.row.col.f32.bf16.bf16.f32 "
        "{%0,%1,%2,%3}, {%4,%5,%6,%7}, {%8,%9}, {%0,%1,%2,%3};"
        : "+f"(c[0]), "+f"(c[1]), "+f"(c[2]), "+f"(c[3])
        : "r"(a[0]), "r"(a[1]), "r"(a[2]), "r"(a[3]), "r"(b0), "r"(b1));
}
__device__ __forceinline__ void cp16(uint32_t dst, const void* src) {
    asm volatile("cp.async.ca.shared.global [%0], [%1], 16;" :: "r"(dst), "l"(src) : "memory");
}
#define CP_COMMIT() asm volatile("cp.async.commit_group;" ::: "memory")
#define CP_WAIT1()  asm volatile("cp.async.wait_group 1;" ::: "memory")
#define CP_WAIT0()  asm volatile("cp.async.wait_group 0;" ::: "memory")

// split two floats into packed bf16x2 hi + lo correction
__device__ __forceinline__ void split2(float a, float b, uint32_t& hi, uint32_t& lo) {
    __nv_bfloat162 h = __floats2bfloat162_rn(a, b);
    float ra = a - __bfloat162float(h.x);
    float rb = b - __bfloat162float(h.y);
    __nv_bfloat162 l = __floats2bfloat162_rn(ra, rb);
    memcpy(&hi, &h, 4);
    memcpy(&lo, &l, 4);
}
__device__ __forceinline__ float actelu(float v) {
    return v > 0.f ? v : (__expf(v) - 1.f);
}

// =====================================================================
// prep kernels
// =====================================================================
__global__ void prep_w1(const float* __restrict__ W1)
{
    int i = blockIdx.x * 256 + threadIdx.x;
    if (i >= 256 * KPAD) return;
    int n = i / KPAD, k = i % KPAD;
    float v = (k < KDIM) ? W1[(size_t)k * HID + n] : 0.f;
    __nv_bfloat16 h = __float2bfloat16_rn(v);
    g_Bhi[i] = h;
    g_Blo[i] = __float2bfloat16_rn(v - __bfloat162float(h));
}

__global__ void prep_gat(const float* __restrict__ W,
                         const float* __restrict__ a_src,
                         const float* __restrict__ a_dst)
{
    int i = blockIdx.x * 256 + threadIdx.x;
    if (i < 12 * 32 * 40) {
        int lh = i / 1280, r = i % 1280, o = r / 40, f = r % 40;
        float v = (o < 26 && f < 26) ? W[((size_t)lh * 26 + f) * 26 + o] : 0.f;
        __nv_bfloat16 h = __float2bfloat16_rn(v);
        g_Wth[i] = h;
        g_Wtl[i] = __float2bfloat16_rn(v - __bfloat162float(h));
    } else {
        int j = i - 12 * 32 * 40;
        if (j < 12 * 32) {
            int lh = j / 32, f = j % 32;
            float s = 0.f, d = 0.f;
            if (f < 26) {
                for (int o = 0; o < 26; o++) {
                    float wv = W[((size_t)lh * 26 + f) * 26 + o];
                    s = fmaf(wv, a_src[lh * 26 + o], s);
                    d = fmaf(wv, a_dst[lh * 26 + o], d);
                }
            }
            g_wsrc[j] = s;
            g_wdst[j] = d;
        }
    }
}

// =====================================================================
// GAT on tensor cores, ONE WARP PER (element, head).
// CTA = 2 elements x 4 heads = 8 warps. Head-mean via smem RED buffers
// that alias each warp's own (dead) alpha region. 3 barriers/layer.
// =====================================================================
#define SM_X    0            // [2 e][hi 2560 | lo 2560] bf16 [32 f][40 j]
#define SM_A    10240        // per warp w: w*5120 (alpha hi | alpha lo), RED aliases
#define SM_W    51200        // hi 10240 | lo 10240, [4 h][32 o][40 f]
#define SM_SD   71680        // sdst: 8 warps * 32 floats
#define SM_WS   72704        // wsrc [4 h][32]
#define SM_WD   73216        // wdst [4 h][32]
#define SM_INV  73728        // sinv: 8 warps * 32 floats
#define GAT_SMEM 74752

__global__ __launch_bounds__(256, 2)
void gat_tc(const float* __restrict__ x)
{
    extern __shared__ char sm[];
    const uint32_t sb = smem_u32(sm);
    const int tid = threadIdx.x, w = tid >> 5, lane = tid & 31;
    const int e = w >> 2, h = w & 3;
    const int b0 = blockIdx.x * 2;
    const int g = lane >> 2, tc2 = (lane & 3) * 2;

    const int rpat = lane & 15;
    const int chalf = (lane >> 4) * 8;

    __nv_bfloat16* xth = (__nv_bfloat16*)(sm + SM_X + e * 5120);
    __nv_bfloat16* xtl = xth + 1280;
    __nv_bfloat16* aph = (__nv_bfloat16*)(sm + SM_A + w * 5120);
    __nv_bfloat16* apl = aph + 1280;
    float* sdst = (float*)(sm + SM_SD) + w * 32;
    float* sinv = (float*)(sm + SM_INV) + w * 32;
    float* redw = (float*)(sm + SM_A + w * 5120);   // aliases own alpha (safe: sequential in-warp)

    const uint32_t xthA = sb + SM_X + e * 5120;
    const uint32_t xtlA = xthA + 2560;
    const uint32_t aphA = sb + SM_A + w * 5120;
    const uint32_t aplA = aphA + 2560;
    const uint32_t WhA  = sb + SM_W + h * 2560;
    const uint32_t WlA  = sb + SM_W + 10240 + h * 2560;

    // zero X region (pads persist through all layers)
    {
        uint4* p = (uint4*)(sm + SM_X);
        for (int i = tid; i < 640; i += 256) p[i] = make_uint4(0, 0, 0, 0);
    }
    __syncthreads();

    // stage x (layer 0) transposed bf16 split: xth[f][j]
    if (tid < 208) {
        int ee = tid / 104, r = tid % 104, j = r >> 2, fq = r & 3;
        int f0 = fq * 7, f1 = (fq == 3) ? 26 : f0 + 7;
        __nv_bfloat16* dxh = (__nv_bfloat16*)(sm + SM_X + ee * 5120);
        __nv_bfloat16* dxl = dxh + 1280;
        const float* src = x + (size_t)(b0 + ee) * KDIM + j * 26;
        for (int f = f0; f < f1; f++) {
            float v = src[f];
            __nv_bfloat16 hh = __float2bfloat16_rn(v);
            dxh[f * 40 + j] = hh;
            dxl[f * 40 + j] = __float2bfloat16_rn(v - __bfloat162float(hh));
        }
    }

    for (int l = 0; l < 3; l++) {
        __syncthreads();   // X ready; W buffer free
        // stage W_l (hi/lo) + score vectors
        {
            const uint4* s0 = (const uint4*)(g_Wth + l * 5120);
            const uint4* s1 = (const uint4*)(g_Wtl + l * 5120);
            uint4* d0 = (uint4*)(sm + SM_W);
            uint4* d1 = (uint4*)(sm + SM_W + 10240);
            for (int i = tid; i < 640; i += 256) { d0[i] = s0[i]; d1[i] = s1[i]; }
            if (tid < 128) {
                ((float*)(sm + SM_WS))[tid] = g_wsrc[l * 128 + tid];
                ((float*)(sm + SM_WD))[tid] = g_wdst[l * 128 + tid];
            }
        }
        __syncthreads();

        // ---- scores for this warp's head: lane = node i ----
        float ssrc;
        {
            const float* sws = (float*)(sm + SM_WS) + h * 32;
            const float* swd = (float*)(sm + SM_WD) + h * 32;
            float s = 0.f, d = 0.f;
            #pragma unroll
            for (int f = 0; f < 26; f++) {
                float xv = __bfloat162float(xth[f * 40 + lane]) +
                           __bfloat162float(xtl[f * 40 + lane]);
                s = fmaf(xv, sws[f], s);
                d = fmaf(xv, swd[f], d);
            }
            ssrc = s;
            sdst[lane] = d;
        }
        __syncwarp();

        // ---- softmax (unnormalized), write alpha rows incl. zero pads ----
        {
            float m = -1e30f;
            #pragma unroll
            for (int j = 0; j < 26; j++) {
                float v = ssrc + sdst[j];
                v = fmaxf(v, 0.2f * v);
                m = fmaxf(m, v);
            }
            float su = 0.f;
            #pragma unroll
            for (int jj = 0; jj < 13; jj++) {
                float v0 = ssrc + sdst[2 * jj];     v0 = fmaxf(v0, 0.2f * v0);
                float v1 = ssrc + sdst[2 * jj + 1]; v1 = fmaxf(v1, 0.2f * v1);
                float p0 = __expf(v0 - m), p1 = __expf(v1 - m);
                su += p0 + p1;
                uint32_t hi, lo;
                split2(p0, p1, hi, lo);
                *(uint32_t*)(aph + lane * 40 + 2 * jj) = hi;
                *(uint32_t*)(apl + lane * 40 + 2 * jj) = lo;
            }
            #pragma unroll
            for (int jj = 13; jj < 20; jj++) {   // re-zero pads (RED clobbered them)
                *(uint32_t*)(aph + lane * 40 + 2 * jj) = 0u;
                *(uint32_t*)(apl + lane * 40 + 2 * jj) = 0u;
            }
            sinv[lane] = 1.f / su;
        }
        __syncwarp();

        // ---- step 1: Y = E @ X^T (3-term split) ----
        float Yf[2][4][4];
        #pragma unroll
        for (int mt = 0; mt < 2; mt++)
            #pragma unroll
            for (int nt = 0; nt < 4; nt++)
                #pragma unroll
                for (int q = 0; q < 4; q++) Yf[mt][nt][q] = 0.f;

        #pragma unroll
        for (int ks = 0; ks < 2; ks++) {
            uint32_t Ah[2][4], Al[2][4], Xh[2][4], Xl[2][4];
            #pragma unroll
            for (int mt = 0; mt < 2; mt++) {
                uint32_t off = (uint32_t)((mt * 16 + rpat) * 80 + (ks * 16 + chalf) * 2);
                ldsm4(Ah[mt], aphA + off);
                ldsm4(Al[mt], aplA + off);
            }
            #pragma unroll
            for (int nt = 0; nt < 2; nt++) {
                uint32_t off = (uint32_t)((nt * 16 + rpat) * 80 + (ks * 16 + chalf) * 2);
                ldsm4(Xh[nt], xthA + off);
                ldsm4(Xl[nt], xtlA + off);
            }
            #pragma unroll
            for (int mt = 0; mt < 2; mt++)
                #pragma unroll
                for (int nt = 0; nt < 2; nt++) {
                    mma16816(Yf[mt][nt * 2],     Ah[mt], Xh[nt][0], Xh[nt][2]);
                    mma16816(Yf[mt][nt * 2 + 1], Ah[mt], Xh[nt][1], Xh[nt][3]);
                    mma16816(Yf[mt][nt * 2],     Ah[mt], Xl[nt][0], Xl[nt][2]);
                    mma16816(Yf[mt][nt * 2 + 1], Ah[mt], Xl[nt][1], Xl[nt][3]);
                    mma16816(Yf[mt][nt * 2],     Al[mt], Xh[nt][0], Xh[nt][2]);
                    mma16816(Yf[mt][nt * 2 + 1], Al[mt], Xh[nt][1], Xh[nt][3]);
                }
        }

        // ---- C->A conversion with 1/sum folded ----
        uint32_t YAh[2][2][4], YAl[2][2][4];
        #pragma unroll
        for (int mt = 0; mt < 2; mt++) {
            const float ia = sinv[mt * 16 + g];
            const float ib = sinv[mt * 16 + g + 8];
            #pragma unroll
            for (int ks = 0; ks < 2; ks++) {
                split2(Yf[mt][2 * ks][0] * ia,     Yf[mt][2 * ks][1] * ia,     YAh[mt][ks][0], YAl[mt][ks][0]);
                split2(Yf[mt][2 * ks][2] * ib,     Yf[mt][2 * ks][3] * ib,     YAh[mt][ks][1], YAl[mt][ks][1]);
                split2(Yf[mt][2 * ks + 1][0] * ia, Yf[mt][2 * ks + 1][1] * ia, YAh[mt][ks][2], YAl[mt][ks][2]);
                split2(Yf[mt][2 * ks + 1][2] * ib, Yf[mt][2 * ks + 1][3] * ib, YAh[mt][ks][3], YAl[mt][ks][3]);
            }
        }

        // ---- step 2: out = Y @ W_h (this head only) ----
        float outf[2][4][4];
        #pragma unroll
        for (int mt = 0; mt < 2; mt++)
            #pragma unroll
            for (int nt = 0; nt < 4; nt++)
                #pragma unroll
                for (int q = 0; q < 4; q++) outf[mt][nt][q] = 0.f;

        #pragma unroll
        for (int ks = 0; ks < 2; ks++) {
            uint32_t Wh[2][4], Wl[2][4];
            #pragma unroll
            for (int ot = 0; ot < 2; ot++) {
                uint32_t off = (uint32_t)((ot * 16 + rpat) * 80 + (ks * 16 + chalf) * 2);
                ldsm4(Wh[ot], WhA + off);
                ldsm4(Wl[ot], WlA + off);
            }
            #pragma unroll
            for (int mt = 0; mt < 2; mt++)
                #pragma unroll
                for (int ot = 0; ot < 2; ot++) {
                    mma16816(outf[mt][ot * 2],     YAh[mt][ks], Wh[ot][0], Wh[ot][2]);
                    mma16816(outf[mt][ot * 2 + 1], YAh[mt][ks], Wh[ot][1], Wh[ot][3]);
                    mma16816(outf[mt][ot * 2],     YAh[mt][ks], Wl[ot][0], Wl[ot][2]);
                    mma16816(outf[mt][ot * 2 + 1], YAh[mt][ks], Wl[ot][1], Wl[ot][3]);
                    mma16816(outf[mt][ot * 2],     YAl[mt][ks], Wh[ot][0], Wh[ot][2]);
                    mma16816(outf[mt][ot * 2 + 1], YAl[mt][ks], Wh[ot][1], Wh[ot][3]);
                }
        }

        // ---- dump head-partial out tile into own RED region ----
        #pragma unroll
        for (int mt = 0; mt < 2; mt++)
            #pragma unroll
            for (int nt = 0; nt < 4; nt++) {
                const int c = nt * 8 + tc2;
                float2 v0; v0.x = outf[mt][nt][0]; v0.y = outf[mt][nt][1];
                float2 v1; v1.x = outf[mt][nt][2]; v1.y = outf[mt][nt][3];
                *(float2*)&redw[(mt * 16 + g) * 32 + c]     = v0;
                *(float2*)&redw[(mt * 16 + g + 8) * 32 + c] = v1;
            }
        __syncthreads();

        // ---- combine: mean over heads + ELU -> next X (or final global) ----
        if (tid < 208) {
            int ee = tid / 104, r = tid % 104, j = r >> 2, fq = r & 3;
            int f0 = fq * 7, f1 = (fq == 3) ? 26 : f0 + 7;
            const float* r0 = (const float*)(sm + SM_A + (ee * 4 + 0) * 5120) + j * 32;
            const float* r1 = (const float*)(sm + SM_A + (ee * 4 + 1) * 5120) + j * 32;
            const float* r2 = (const float*)(sm + SM_A + (ee * 4 + 2) * 5120) + j * 32;
            const float* r3 = (const float*)(sm + SM_A + (ee * 4 + 3) * 5120) + j * 32;
            if (l < 2) {
                __nv_bfloat16* dxh = (__nv_bfloat16*)(sm + SM_X + ee * 5120);
                __nv_bfloat16* dxl = dxh + 1280;
                for (int f = f0; f < f1; f++) {
                    float v = actelu(0.25f * (r0[f] + r1[f] + r2[f] + r3[f]));
                    __nv_bfloat16 hh = __float2bfloat16_rn(v);
                    dxh[f * 40 + j] = hh;
                    dxl[f * 40 + j] = __float2bfloat16_rn(v - __bfloat162float(hh));
                }
            } else {
                size_t o = (size_t)(b0 + ee) * KPAD + j * 26;
                for (int f = f0; f < f1; f++) {
                    float v = actelu(0.25f * (r0[f] + r1[f] + r2[f] + r3[f]));
                    __nv_bfloat16 hh = __float2bfloat16_rn(v);
                    g_Ahi[o + f] = hh;
                    g_Alo[o + f] = __float2bfloat16_rn(v - __bfloat162float(hh));
                }
            }
        }
        if (l == 2 && tid < 56) {
            int ee = tid / 28, c = tid % 28;
            g_Ahi[(size_t)(b0 + ee) * KPAD + KDIM + c] = __float2bfloat16_rn(0.f);
            g_Alo[(size_t)(b0 + ee) * KPAD + KDIM + c] = __float2bfloat16_rn(0.f);
        }
    } // layers
}

// =====================================================================
// MLP via mma.sync bf16 (3-term split) — unchanged (passing since R4).
// =====================================================================
#define STAGE_BYTES 51200
#define MLP_SMEM (2 * STAGE_BYTES)

__device__ __forceinline__ void copy_chunk(uint32_t smbase, int stage, int chunk,
                                           int row0, int tid)
{
    const uint32_t sbs = smbase + stage * STAGE_BYTES;
    #pragma unroll
    for (int k = 0; k < 10; k++) {
        int u = tid + k * 256;
        if (u < 512) {
            int t = u >> 8, r = (u & 255) >> 2, seg = u & 3;
            const __nv_bfloat16* base = t ? g_Alo : g_Ahi;
            const __nv_bfloat16* src = base + (size_t)(row0 + r) * KPAD + chunk * 32 + seg * 8;
            cp16(sbs + t * 5120 + r * 80 + seg * 16, src);
        } else {
            int v = u - 512;
            int t = v >> 10, r = (v & 1023) >> 2, seg = v & 3;
            const __nv_bfloat16* base = t ? g_Blo : g_Bhi;
            const __nv_bfloat16* src = base + (size_t)r * KPAD + chunk * 32 + seg * 8;
            cp16(sbs + 10240 + t * 20480 + r * 80 + seg * 16, src);
        }
    }
}

__global__ __launch_bounds__(256, 2)
void mlp_mma(const float* __restrict__ b1,
             const float* __restrict__ W2,
             const float* __restrict__ b2,
             float* __restrict__ out)
{
    extern __shared__ __align__(16) char dsm[];
    __shared__ float sb1[HID];
    __shared__ float sW2[HID * 3];
    __shared__ float sb2s[3];
    __shared__ float red[64][13];

    const int tid = threadIdx.x, wid = tid >> 5, lane = tid & 31;
    const int warp_m = wid & 1;
    const int warp_n = wid >> 1;
    const int row0 = blockIdx.x * 64;

    if (tid < HID) sb1[tid] = b1[tid];
    for (int i = tid; i < HID * 3; i += 256) sW2[i] = W2[i];
    if (tid < 3) sb2s[tid] = b2[tid];

    const uint32_t smbase = smem_u32(dsm);

    float acc[2][8][4];
    #pragma unroll
    for (int mt = 0; mt < 2; mt++)
        #pragma unroll
        for (int nt = 0; nt < 8; nt++)
            #pragma unroll
            for (int q = 0; q < 4; q++) acc[mt][nt][q] = 0.f;

    copy_chunk(smbase, 0, 0, row0, tid);
    CP_COMMIT();

    const int rpat = lane & 15;

    for (int c = 0; c < NCHUNK; c++) {
        const int s = c & 1;
        if (c + 1 < NCHUNK) {
            copy_chunk(smbase, s ^ 1, c + 1, row0, tid);
            CP_COMMIT();
            CP_WAIT1();
        } else {
            CP_WAIT0();
        }
        __syncthreads();

        const uint32_t stB = smbase + s * STAGE_BYTES;
        #pragma unroll
        for (int ks = 0; ks < 2; ks++) {
            const int cpat = ks * 16 + (lane >> 4) * 8;

            uint32_t ah[2][4], al[2][4];
            #pragma unroll
            for (int mt = 0; mt < 2; mt++) {
                const uint32_t a_off =
                    (uint32_t)((warp_m * 32 + mt * 16 + rpat) * 80 + cpat * 2);
                ldsm4(ah[mt], stB + a_off);
                ldsm4(al[mt], stB + 5120 + a_off);
            }

            uint32_t bf[4][4];
            #pragma unroll
            for (int np = 0; np < 4; np++) {
                const uint32_t b_off =
                    (uint32_t)((warp_n * 64 + np * 16 + rpat) * 80 + cpat * 2);
                ldsm4(bf[np], stB + 10240 + b_off);
            }
            #pragma unroll
            for (int mt = 0; mt < 2; mt++)
                #pragma unroll
                for (int np = 0; np < 4; np++) {
                    mma16816(acc[mt][np * 2 + 0], ah[mt], bf[np][0], bf[np][2]);
                    mma16816(acc[mt][np * 2 + 1], ah[mt], bf[np][1], bf[np][3]);
                    mma16816(acc[mt][np * 2 + 0], al[mt], bf[np][0], bf[np][2]);
                    mma16816(acc[mt][np * 2 + 1], al[mt], bf[np][1], bf[np][3]);
                }
            #pragma unroll
            for (int np = 0; np < 4; np++) {
                const uint32_t b_off =
                    (uint32_t)((warp_n * 64 + np * 16 + rpat) * 80 + cpat * 2);
                ldsm4(bf[np], stB + 30720 + b_off);
            }
            #pragma unroll
            for (int mt = 0; mt < 2; mt++)
                #pragma unroll
                for (int np = 0; np < 4; np++) {
                    mma16816(acc[mt][np * 2 + 0], ah[mt], bf[np][0], bf[np][2]);
                    mma16816(acc[mt][np * 2 + 1], ah[mt], bf[np][1], bf[np][3]);
                }
        }
        __syncthreads();
    }

    #pragma unroll
    for (int mt = 0; mt < 2; mt++) {
        #pragma unroll
        for (int half = 0; half < 2; half++) {
            float s0 = 0.f, s1 = 0.f, s2 = 0.f;
            #pragma unroll
            for (int nt = 0; nt < 8; nt++) {
                const int col = warp_n * 64 + nt * 8 + (lane & 3) * 2;
                float v0 = acc[mt][nt][half * 2 + 0] + sb1[col];
                v0 = fmaxf(v0, 0.2f * v0);
                float v1 = acc[mt][nt][half * 2 + 1] + sb1[col + 1];
                v1 = fmaxf(v1, 0.2f * v1);
                s0 += v0 * sW2[col * 3 + 0] + v1 * sW2[(col + 1) * 3 + 0];
                s1 += v0 * sW2[col * 3 + 1] + v1 * sW2[(col + 1) * 3 + 1];
                s2 += v0 * sW2[col * 3 + 2] + v1 * sW2[(col + 1) * 3 + 2];
            }
            s0 += __shfl_xor_sync(0xffffffffu, s0, 1);
            s0 += __shfl_xor_sync(0xffffffffu, s0, 2);
            s1 += __shfl_xor_sync(0xffffffffu, s1, 1);
            s1 += __shfl_xor_sync(0xffffffffu, s1, 2);
            s2 += __shfl_xor_sync(0xffffffffu, s2, 1);
            s2 += __shfl_xor_sync(0xffffffffu, s2, 2);
            if ((lane & 3) == 0) {
                const int row = warp_m * 32 + mt * 16 + half * 8 + (lane >> 2);
                red[row][warp_n * 3 + 0] = s0;
                red[row][warp_n * 3 + 1] = s1;
                red[row][warp_n * 3 + 2] = s2;
            }
        }
    }
    __syncthreads();
    if (tid < 64) {
        const int row = tid;
        #pragma unroll
        for (int oc = 0; oc < 3; oc++) {
            float v = red[row][oc] + red[row][3 + oc] + red[row][6 + oc] +
                      red[row][9 + oc] + sb2s[oc];
            out[(size_t)(row0 + row) * 3 + oc] = v;
        }
    }
}

// =====================================================================
// launch
// =====================================================================
extern "C" void kernel_launch(void* const* d_in, const int* in_sizes, int n_in,
                              void* d_out, int out_size)
{
    const float* x     = (const float*)d_in[1];
    const float* W     = (const float*)d_in[2];
    const float* a_src = (const float*)d_in[3];
    const float* a_dst = (const float*)d_in[4];
    const float* W1    = (const float*)d_in[5];
    const float* b1    = (const float*)d_in[6];
    const float* W2    = (const float*)d_in[7];
    const float* b2    = (const float*)d_in[8];
    float* out = (float*)d_out;

    const int batch = in_sizes[1] / KDIM;   // 16384

    cudaFuncSetAttribute(gat_tc, cudaFuncAttributeMaxDynamicSharedMemorySize, GAT_SMEM);
    cudaFuncSetAttribute(mlp_mma, cudaFuncAttributeMaxDynamicSharedMemorySize, MLP_SMEM);

    prep_w1<<<(256 * KPAD + 255) / 256, 256>>>(W1);
    prep_gat<<<(12 * 32 * 40 + 12 * 32 + 255) / 256, 256>>>(W, a_src, a_dst);
    gat_tc<<<batch / 2, 256, GAT_SMEM>>>(x);
    mlp_mma<<<batch / 64, 256, MLP_SMEM>>>(b1, W2, b2, out);
    (void)n_in; (void)out_size;
}

// round 8
// speedup vs baseline: 1.4048x; 1.4048x over previous
#include <cuda_runtime.h>
#include <cuda_bf16.h>
#include <cstdint>
#include <cstddef>
#include <cstring>

// ---------------- problem constants ----------------
#define NN       26
#define KDIM     676
#define KPAD     704          // 22 * 32
#define NCHUNK   22
#define HID      256

// GAT output as bf16 hi/lo split [B, KPAD]
__device__ __nv_bfloat16 g_Ahi[16384 * KPAD];
__device__ __nv_bfloat16 g_Alo[16384 * KPAD];
// W1^T split: [256 n][KPAD k]
__device__ __nv_bfloat16 g_Bhi[256 * KPAD];
__device__ __nv_bfloat16 g_Blo[256 * KPAD];
// GAT weights, transposed + padded + split: [12 lh][32 o][40 f]
__device__ __nv_bfloat16 g_Wth[12 * 32 * 40];
__device__ __nv_bfloat16 g_Wtl[12 * 32 * 40];
// score vectors wsrc/wdst = W @ a_*: [12 lh][32 f]
__device__ float g_wsrc[12 * 32];
__device__ float g_wdst[12 * 32];

// ---------------- common helpers ----------------
__device__ __forceinline__ uint32_t smem_u32(const void* p) {
    uint32_t a;
    asm("{ .reg .u64 t; cvta.to.shared.u64 t, %1; cvt.u32.u64 %0, t; }" : "=r"(a) : "l"(p));
    return a;
}
__device__ __forceinline__ void ldsm4(uint32_t* d, uint32_t addr) {
    asm volatile("ldmatrix.sync.aligned.m8n8.x4.shared.b16 {%0,%1,%2,%3}, [%4];"
                 : "=r"(d[0]), "=r"(d[1]), "=r"(d[2]), "=r"(d[3]) : "r"(addr));
}
__device__ __forceinline__ void mma16816(float* c, const uint32_t* a, uint32_t b0, uint32_t b1) {
    asm volatile(
        "mma.sync.aligned.m16n8k16.row.col.f32.bf16.bf16.f32 "
        "{%0,%1,%2,%3}, {%4,%5,%6,%7}, {%8,%9}, {%0,%1,%2,%3};"
        : "+f"(c[0]), "+f"(c[1]), "+f"(c[2]), "+f"(c[3])
        : "r"(a[0]), "r"(a[1]), "r"(a[2]), "r"(a[3]), "r"(b0), "r"(b1));
}
__device__ __forceinline__ void cp16(uint32_t dst, const void* src) {
    asm volatile("cp.async.ca.shared.global [%0], [%1], 16;" :: "r"(dst), "l"(src) : "memory");
}
#define CP_COMMIT() asm volatile("cp.async.commit_group;" ::: "memory")
#define CP_WAIT1()  asm volatile("cp.async.wait_group 1;" ::: "memory")
#define CP_WAIT0()  asm volatile("cp.async.wait_group 0;" ::: "memory")

// split two floats into packed bf16x2 hi + lo correction
__device__ __forceinline__ void split2(float a, float b, uint32_t& hi, uint32_t& lo) {
    __nv_bfloat162 h = __floats2bfloat162_rn(a, b);
    float ra = a - __bfloat162float(h.x);
    float rb = b - __bfloat162float(h.y);
    __nv_bfloat162 l = __floats2bfloat162_rn(ra, rb);
    memcpy(&hi, &h, 4);
    memcpy(&lo, &l, 4);
}
__device__ __forceinline__ float actelu(float v) {
    return v > 0.f ? v : (__expf(v) - 1.f);
}

// =====================================================================
// merged prep kernel
// =====================================================================
__global__ void prep_all(const float* __restrict__ W1,
                         const float* __restrict__ W,
                         const float* __restrict__ a_src,
                         const float* __restrict__ a_dst)
{
    int i = blockIdx.x * 256 + threadIdx.x;
    if (i < 256 * KPAD) {
        int n = i / KPAD, k = i % KPAD;
        float v = (k < KDIM) ? W1[(size_t)k * HID + n] : 0.f;
        __nv_bfloat16 h = __float2bfloat16_rn(v);
        g_Bhi[i] = h;
        g_Blo[i] = __float2bfloat16_rn(v - __bfloat162float(h));
        return;
    }
    int u = i - 256 * KPAD;
    if (u < 12 * 32 * 40) {
        int lh = u / 1280, r = u % 1280, o = r / 40, f = r % 40;
        float v = (o < 26 && f < 26) ? W[((size_t)lh * 26 + f) * 26 + o] : 0.f;
        __nv_bfloat16 h = __float2bfloat16_rn(v);
        g_Wth[u] = h;
        g_Wtl[u] = __float2bfloat16_rn(v - __bfloat162float(h));
        return;
    }
    int j = u - 12 * 32 * 40;
    if (j < 12 * 32) {
        int lh = j / 32, f = j % 32;
        float s = 0.f, d = 0.f;
        if (f < 26) {
            for (int o = 0; o < 26; o++) {
                float wv = W[((size_t)lh * 26 + f) * 26 + o];
                s = fmaf(wv, a_src[lh * 26 + o], s);
                d = fmaf(wv, a_dst[lh * 26 + o], d);
            }
        }
        g_wsrc[j] = s;
        g_wdst[j] = d;
    }
}

// =====================================================================
// GAT on tensor cores (R5 structure, best measured): warp = element,
// 8 warps/block, alpha/x/W all bf16 hi/lo 3-term split.
// =====================================================================
#define XTH 0
#define XTL 20480
#define APH 40960
#define APL 61440
#define WTH 81920
#define WTL 92160
#define SDST 102400
#define SWS 106496
#define SWD 107008
#define GAT_SMEM 107520

__global__ __launch_bounds__(256, 2)
void gat_tc(const float* __restrict__ x)
{
    extern __shared__ char sm[];
    const uint32_t sb = smem_u32(sm);
    const int tid = threadIdx.x, w = tid >> 5, lane = tid & 31;
    const int b = blockIdx.x * 8 + w;

    // zero xT buffers once (pads stay zero forever)
    {
        uint4* p = (uint4*)(sm + XTH);
        for (int i = tid; i < (20480 * 2) / 16; i += 256)
            p[i] = make_uint4(0, 0, 0, 0);
    }
    __syncthreads();

    __nv_bfloat16* xth = (__nv_bfloat16*)(sm + XTH) + w * 1280;   // [32 f][40 j]
    __nv_bfloat16* xtl = (__nv_bfloat16*)(sm + XTL) + w * 1280;
    __nv_bfloat16* aph = (__nv_bfloat16*)(sm + APH) + w * 1280;   // [32 i][40 j]
    __nv_bfloat16* apl = (__nv_bfloat16*)(sm + APL) + w * 1280;
    float* sdst = (float*)(sm + SDST) + w * 128;                  // [4 h][32 j]
    float* sws  = (float*)(sm + SWS);                             // [4 h][32 f]
    float* swd  = (float*)(sm + SWD);

    // stage x (layer 0): transposed bf16 split
    for (int idx = lane; idx < KDIM; idx += 32) {
        int i = idx / 26, f = idx % 26;
        float v = x[(size_t)b * KDIM + idx];
        __nv_bfloat16 h = __float2bfloat16_rn(v);
        xth[f * 40 + i] = h;
        xtl[f * 40 + i] = __float2bfloat16_rn(v - __bfloat162float(h));
    }

    const int rpat = lane & 15;
    const int chalf = (lane >> 4) * 8;
    const uint32_t xthA = sb + XTH + w * 2560;
    const uint32_t xtlA = sb + XTL + w * 2560;
    const uint32_t aphA = sb + APH + w * 2560;
    const uint32_t aplA = sb + APL + w * 2560;

    for (int l = 0; l < 3; l++) {
        __syncthreads();   // xT writes done; W buffer free
        {
            const uint4* s0 = (const uint4*)(g_Wth + l * 5120);
            const uint4* s1 = (const uint4*)(g_Wtl + l * 5120);
            uint4* d0 = (uint4*)(sm + WTH);
            uint4* d1 = (uint4*)(sm + WTL);
            for (int i = tid; i < 640; i += 256) { d0[i] = s0[i]; d1[i] = s1[i]; }
            if (tid < 128) {
                ((float*)(sm + SWS))[tid] = g_wsrc[l * 128 + tid];
                ((float*)(sm + SWD))[tid] = g_wdst[l * 128 + tid];
            }
        }
        __syncthreads();

        // ---- scores: lane = node index ----
        float ssrc[4];
        {
            float xi[26];
            #pragma unroll
            for (int f = 0; f < 26; f++)
                xi[f] = __bfloat162float(xth[f * 40 + lane]) +
                        __bfloat162float(xtl[f * 40 + lane]);
            #pragma unroll
            for (int h = 0; h < 4; h++) {
                float s = 0.f, d = 0.f;
                #pragma unroll
                for (int f = 0; f < 26; f++) {
                    s = fmaf(xi[f], sws[h * 32 + f], s);
                    d = fmaf(xi[f], swd[h * 32 + f], d);
                }
                ssrc[h] = s;
                sdst[h * 32 + lane] = d;
            }
        }
        __syncwarp();

        float outf[2][4][4];
        #pragma unroll
        for (int mt = 0; mt < 2; mt++)
            #pragma unroll
            for (int nt = 0; nt < 4; nt++)
                #pragma unroll
                for (int q = 0; q < 4; q++) outf[mt][nt][q] = 0.f;

        for (int h = 0; h < 4; h++) {
            // ---- softmax row (lane = i) ----
            float e[NN];
            float m = -1e30f;
            #pragma unroll
            for (int j = 0; j < NN; j++) {
                float v = ssrc[h] + sdst[h * 32 + j];
                v = fmaxf(v, 0.2f * v);
                e[j] = v;
                m = fmaxf(m, v);
            }
            float su = 0.f;
            #pragma unroll
            for (int j = 0; j < NN; j++) {
                float p = __expf(e[j] - m);
                e[j] = p;
                su += p;
            }
            const float inv = 1.0f / su;
            #pragma unroll
            for (int jj = 0; jj < 16; jj++) {
                float a0 = (2 * jj < 26) ? e[(2 * jj < 26) ? 2 * jj : 0] * inv : 0.f;
                float a1 = (2 * jj + 1 < 26) ? e[(2 * jj + 1 < 26) ? 2 * jj + 1 : 0] * inv : 0.f;
                uint32_t hi, lo;
                split2(a0, a1, hi, lo);
                *(uint32_t*)(aph + lane * 40 + 2 * jj) = hi;
                *(uint32_t*)(apl + lane * 40 + 2 * jj) = lo;
            }
            __syncwarp();

            // ---- step 1: Y = alpha @ x  (3-term split) ----
            float Yf[2][4][4];
            #pragma unroll
            for (int mt = 0; mt < 2; mt++)
                #pragma unroll
                for (int nt = 0; nt < 4; nt++)
                    #pragma unroll
                    for (int q = 0; q < 4; q++) Yf[mt][nt][q] = 0.f;

            #pragma unroll
            for (int ks = 0; ks < 2; ks++) {
                uint32_t Ah[2][4], Al[2][4], Xh[2][4], Xl[2][4];
                #pragma unroll
                for (int mt = 0; mt < 2; mt++) {
                    uint32_t off = (uint32_t)((mt * 16 + rpat) * 80 + (ks * 16 + chalf) * 2);
                    ldsm4(Ah[mt], aphA + off);
                    ldsm4(Al[mt], aplA + off);
                }
                #pragma unroll
                for (int nt = 0; nt < 2; nt++) {
                    uint32_t off = (uint32_t)((nt * 16 + rpat) * 80 + (ks * 16 + chalf) * 2);
                    ldsm4(Xh[nt], xthA + off);
                    ldsm4(Xl[nt], xtlA + off);
                }
                #pragma unroll
                for (int mt = 0; mt < 2; mt++)
                    #pragma unroll
                    for (int nt = 0; nt < 2; nt++) {
                        mma16816(Yf[mt][nt * 2],     Ah[mt], Xh[nt][0], Xh[nt][2]);
                        mma16816(Yf[mt][nt * 2 + 1], Ah[mt], Xh[nt][1], Xh[nt][3]);
                        mma16816(Yf[mt][nt * 2],     Ah[mt], Xl[nt][0], Xl[nt][2]);
                        mma16816(Yf[mt][nt * 2 + 1], Ah[mt], Xl[nt][1], Xl[nt][3]);
                        mma16816(Yf[mt][nt * 2],     Al[mt], Xh[nt][0], Xh[nt][2]);
                        mma16816(Yf[mt][nt * 2 + 1], Al[mt], Xh[nt][1], Xh[nt][3]);
                    }
            }

            // ---- in-register C -> A fragment conversion (split) ----
            uint32_t YAh[2][2][4], YAl[2][2][4];
            #pragma unroll
            for (int mt = 0; mt < 2; mt++)
                #pragma unroll
                for (int ks = 0; ks < 2; ks++) {
                    split2(Yf[mt][2 * ks][0],     Yf[mt][2 * ks][1],     YAh[mt][ks][0], YAl[mt][ks][0]);
                    split2(Yf[mt][2 * ks][2],     Yf[mt][2 * ks][3],     YAh[mt][ks][1], YAl[mt][ks][1]);
                    split2(Yf[mt][2 * ks + 1][0], Yf[mt][2 * ks + 1][1], YAh[mt][ks][2], YAl[mt][ks][2]);
                    split2(Yf[mt][2 * ks + 1][2], Yf[mt][2 * ks + 1][3], YAh[mt][ks][3], YAl[mt][ks][3]);
                }

            // ---- step 2: out += Y @ W_h ----
            #pragma unroll
            for (int ks = 0; ks < 2; ks++) {
                uint32_t Wh[2][4], Wl[2][4];
                #pragma unroll
                for (int ot = 0; ot < 2; ot++) {
                    uint32_t off = (uint32_t)((ot * 16 + rpat) * 80 + (ks * 16 + chalf) * 2);
                    ldsm4(Wh[ot], sb + WTH + h * 2560 + off);
                    ldsm4(Wl[ot], sb + WTL + h * 2560 + off);
                }
                #pragma unroll
                for (int mt = 0; mt < 2; mt++)
                    #pragma unroll
                    for (int ot = 0; ot < 2; ot++) {
                        mma16816(outf[mt][ot * 2],     YAh[mt][ks], Wh[ot][0], Wh[ot][2]);
                        mma16816(outf[mt][ot * 2 + 1], YAh[mt][ks], Wh[ot][1], Wh[ot][3]);
                        mma16816(outf[mt][ot * 2],     YAh[mt][ks], Wl[ot][0], Wl[ot][2]);
                        mma16816(outf[mt][ot * 2 + 1], YAh[mt][ks], Wl[ot][1], Wl[ot][3]);
                        mma16816(outf[mt][ot * 2],     YAl[mt][ks], Wh[ot][0], Wh[ot][2]);
                        mma16816(outf[mt][ot * 2 + 1], YAl[mt][ks], Wh[ot][1], Wh[ot][3]);
                    }
            }
        } // heads

        // ---- epilogue: mean + ELU, write next xT or final global split ----
        const int g = lane >> 2, tc2 = (lane & 3) * 2;
        if (l < 2) {
            #pragma unroll
            for (int mt = 0; mt < 2; mt++)
                #pragma unroll
                for (int nt = 0; nt < 4; nt++) {
                    int col = nt * 8 + tc2;
                    if (col < 26) {
                        #pragma unroll
                        for (int hf = 0; hf < 2; hf++) {
                            int row = mt * 16 + g + hf * 8;
                            if (row < 26) {
                                float v0 = actelu(outf[mt][nt][hf * 2]     * 0.25f);
                                float v1 = actelu(outf[mt][nt][hf * 2 + 1] * 0.25f);
                                __nv_bfloat16 h0 = __float2bfloat16_rn(v0);
                                __nv_bfloat16 h1 = __float2bfloat16_rn(v1);
                                xth[col * 40 + row] = h0;
                                xtl[col * 40 + row] = __float2bfloat16_rn(v0 - __bfloat162float(h0));
                                xth[(col + 1) * 40 + row] = h1;
                                xtl[(col + 1) * 40 + row] = __float2bfloat16_rn(v1 - __bfloat162float(h1));
                            }
                        }
                    }
                }
        } else {
            #pragma unroll
            for (int mt = 0; mt < 2; mt++)
                #pragma unroll
                for (int nt = 0; nt < 4; nt++) {
                    int col = nt * 8 + tc2;
                    if (col < 26) {
                        #pragma unroll
                        for (int hf = 0; hf < 2; hf++) {
                            int row = mt * 16 + g + hf * 8;
                            if (row < 26) {
                                float v0 = actelu(outf[mt][nt][hf * 2]     * 0.25f);
                                float v1 = actelu(outf[mt][nt][hf * 2 + 1] * 0.25f);
                                uint32_t hi, lo;
                                split2(v0, v1, hi, lo);
                                size_t o = (size_t)b * KPAD + row * 26 + col;
                                *(uint32_t*)&g_Ahi[o] = hi;
                                *(uint32_t*)&g_Alo[o] = lo;
                            }
                        }
                    }
                }
            if (lane < 28) {
                g_Ahi[(size_t)b * KPAD + KDIM + lane] = __float2bfloat16_rn(0.f);
                g_Alo[(size_t)b * KPAD + KDIM + lane] = __float2bfloat16_rn(0.f);
            }
        }
    } // layers
}

// =====================================================================
// MLP via mma.sync bf16 (3-term split). Change vs R5: ALL 12 ldsm4 per
// k-step hoisted ahead of the 48 MMAs (no mid-sequence LDS stall).
// =====================================================================
#define STAGE_BYTES 51200
#define MLP_SMEM (2 * STAGE_BYTES)

__device__ __forceinline__ void copy_chunk(uint32_t smbase, int stage, int chunk,
                                           int row0, int tid)
{
    const uint32_t sbs = smbase + stage * STAGE_BYTES;
    #pragma unroll
    for (int k = 0; k < 10; k++) {
        int u = tid + k * 256;
        if (u < 512) {
            int t = u >> 8, r = (u & 255) >> 2, seg = u & 3;
            const __nv_bfloat16* base = t ? g_Alo : g_Ahi;
            const __nv_bfloat16* src = base + (size_t)(row0 + r) * KPAD + chunk * 32 + seg * 8;
            cp16(sbs + t * 5120 + r * 80 + seg * 16, src);
        } else {
            int v = u - 512;
            int t = v >> 10, r = (v & 1023) >> 2, seg = v & 3;
            const __nv_bfloat16* base = t ? g_Blo : g_Bhi;
            const __nv_bfloat16* src = base + (size_t)r * KPAD + chunk * 32 + seg * 8;
            cp16(sbs + 10240 + t * 20480 + r * 80 + seg * 16, src);
        }
    }
}

__global__ __launch_bounds__(256, 2)
void mlp_mma(const float* __restrict__ b1,
             const float* __restrict__ W2,
             const float* __restrict__ b2,
             float* __restrict__ out)
{
    extern __shared__ __align__(16) char dsm[];
    __shared__ float sb1[HID];
    __shared__ float sW2[HID * 3];
    __shared__ float sb2s[3];
    __shared__ float red[64][13];

    const int tid = threadIdx.x, wid = tid >> 5, lane = tid & 31;
    const int warp_m = wid & 1;
    const int warp_n = wid >> 1;
    const int row0 = blockIdx.x * 64;

    if (tid < HID) sb1[tid] = b1[tid];
    for (int i = tid; i < HID * 3; i += 256) sW2[i] = W2[i];
    if (tid < 3) sb2s[tid] = b2[tid];

    const uint32_t smbase = smem_u32(dsm);

    float acc[2][8][4];
    #pragma unroll
    for (int mt = 0; mt < 2; mt++)
        #pragma unroll
        for (int nt = 0; nt < 8; nt++)
            #pragma unroll
            for (int q = 0; q < 4; q++) acc[mt][nt][q] = 0.f;

    copy_chunk(smbase, 0, 0, row0, tid);
    CP_COMMIT();

    const int rpat = lane & 15;

    for (int c = 0; c < NCHUNK; c++) {
        const int s = c & 1;
        if (c + 1 < NCHUNK) {
            copy_chunk(smbase, s ^ 1, c + 1, row0, tid);
            CP_COMMIT();
            CP_WAIT1();
        } else {
            CP_WAIT0();
        }
        __syncthreads();

        const uint32_t stB = smbase + s * STAGE_BYTES;
        #pragma unroll
        for (int ks = 0; ks < 2; ks++) {
            const int cpat = ks * 16 + (lane >> 4) * 8;

            // ---- hoist ALL fragment loads for this k-step ----
            uint32_t ah[2][4], al[2][4], bh[4][4], bl[4][4];
            #pragma unroll
            for (int mt = 0; mt < 2; mt++) {
                const uint32_t a_off =
                    (uint32_t)((warp_m * 32 + mt * 16 + rpat) * 80 + cpat * 2);
                ldsm4(ah[mt], stB + a_off);
                ldsm4(al[mt], stB + 5120 + a_off);
            }
            #pragma unroll
            for (int np = 0; np < 4; np++) {
                const uint32_t b_off =
                    (uint32_t)((warp_n * 64 + np * 16 + rpat) * 80 + cpat * 2);
                ldsm4(bh[np], stB + 10240 + b_off);
                ldsm4(bl[np], stB + 30720 + b_off);
            }

            // ---- 48 MMAs, no intervening loads ----
            #pragma unroll
            for (int mt = 0; mt < 2; mt++)
                #pragma unroll
                for (int np = 0; np < 4; np++) {
                    mma16816(acc[mt][np * 2 + 0], ah[mt], bh[np][0], bh[np][2]);
                    mma16816(acc[mt][np * 2 + 1], ah[mt], bh[np][1], bh[np][3]);
                    mma16816(acc[mt][np * 2 + 0], al[mt], bh[np][0], bh[np][2]);
                    mma16816(acc[mt][np * 2 + 1], al[mt], bh[np][1], bh[np][3]);
                    mma16816(acc[mt][np * 2 + 0], ah[mt], bl[np][0], bl[np][2]);
                    mma16816(acc[mt][np * 2 + 1], ah[mt], bl[np][1], bl[np][3]);
                }
        }
        __syncthreads();
    }

    #pragma unroll
    for (int mt = 0; mt < 2; mt++) {
        #pragma unroll
        for (int half = 0; half < 2; half++) {
            float s0 = 0.f, s1 = 0.f, s2 = 0.f;
            #pragma unroll
            for (int nt = 0; nt < 8; nt++) {
                const int col = warp_n * 64 + nt * 8 + (lane & 3) * 2;
                float v0 = acc[mt][nt][half * 2 + 0] + sb1[col];
                v0 = fmaxf(v0, 0.2f * v0);
                float v1 = acc[mt][nt][half * 2 + 1] + sb1[col + 1];
                v1 = fmaxf(v1, 0.2f * v1);
                s0 += v0 * sW2[col * 3 + 0] + v1 * sW2[(col + 1) * 3 + 0];
                s1 += v0 * sW2[col * 3 + 1] + v1 * sW2[(col + 1) * 3 + 1];
                s2 += v0 * sW2[col * 3 + 2] + v1 * sW2[(col + 1) * 3 + 2];
            }
            s0 += __shfl_xor_sync(0xffffffffu, s0, 1);
            s0 += __shfl_xor_sync(0xffffffffu, s0, 2);
            s1 += __shfl_xor_sync(0xffffffffu, s1, 1);
            s1 += __shfl_xor_sync(0xffffffffu, s1, 2);
            s2 += __shfl_xor_sync(0xffffffffu, s2, 1);
            s2 += __shfl_xor_sync(0xffffffffu, s2, 2);
            if ((lane & 3) == 0) {
                const int row = warp_m * 32 + mt * 16 + half * 8 + (lane >> 2);
                red[row][warp_n * 3 + 0] = s0;
                red[row][warp_n * 3 + 1] = s1;
                red[row][warp_n * 3 + 2] = s2;
            }
        }
    }
    __syncthreads();
    if (tid < 64) {
        const int row = tid;
        #pragma unroll
        for (int oc = 0; oc < 3; oc++) {
            float v = red[row][oc] + red[row][3 + oc] + red[row][6 + oc] +
                      red[row][9 + oc] + sb2s[oc];
            out[(size_t)(row0 + row) * 3 + oc] = v;
        }
    }
}

// =====================================================================
// launch
// =====================================================================
extern "C" void kernel_launch(void* const* d_in, const int* in_sizes, int n_in,
                              void* d_out, int out_size)
{
    const float* x     = (const float*)d_in[1];
    const float* W     = (const float*)d_in[2];
    const float* a_src = (const float*)d_in[3];
    const float* a_dst = (const float*)d_in[4];
    const float* W1    = (const float*)d_in[5];
    const float* b1    = (const float*)d_in[6];
    const float* W2    = (const float*)d_in[7];
    const float* b2    = (const float*)d_in[8];
    float* out = (float*)d_out;

    const int batch = in_sizes[1] / KDIM;   // 16384

    cudaFuncSetAttribute(gat_tc, cudaFuncAttributeMaxDynamicSharedMemorySize, GAT_SMEM);
    cudaFuncSetAttribute(mlp_mma, cudaFuncAttributeMaxDynamicSharedMemorySize, MLP_SMEM);

    const int prep_total = 256 * KPAD + 12 * 32 * 40 + 12 * 32;
    prep_all<<<(prep_total + 255) / 256, 256>>>(W1, W, a_src, a_dst);
    gat_tc<<<batch / 8, 256, GAT_SMEM>>>(x);
    mlp_mma<<<batch / 64, 256, MLP_SMEM>>>(b1, W2, b2, out);
    (void)n_in; (void)out_size;
}